// round 1
// baseline (speedup 1.0000x reference)
#include <cuda_runtime.h>
#include <cuda_bf16.h>

// Problem constants (fixed by the reference)
#define NB   1024      // batch
#define NS1  25        // hop-1 fanout
#define NS2  10        // hop-2 fanout
#define ND   256       // feature dim
#define NH   128       // per-branch hidden
#define NC   64        // classes
#define M1   (NB*NS1)  // 25600

// Scratch (no cudaMalloc allowed -> __device__ globals)
__device__ float g_m1[M1 * ND];   // mean over S2 of hop-2 features   [25600,256]
__device__ float g_m0[NB * ND];   // mean over S1 of hop-1 features   [1024,256]
__device__ float g_g1[M1 * ND];   // layer-1 output on hop-1 set      [25600,256]
__device__ float g_g0[NB * ND];   // layer-1 output on batch set      [1024,256]
__device__ float g_gm[NB * ND];   // mean over S1 of g1               [1024,256]
__device__ float g_f0[NB * ND];   // layer-2 output                   [1024,256]

// ---------------------------------------------------------------------------
// mean over `fanout` rows of src (optionally indirected through ids)
// grid = #groups, block = 256 (one thread per feature column)
// ---------------------------------------------------------------------------
__global__ void mean_gather(const float* __restrict__ src,
                            const int* __restrict__ ids,
                            float* __restrict__ dst,
                            int fanout, float inv)
{
    const int g = blockIdx.x;
    const int t = threadIdx.x;
    const long base = (long)g * fanout;
    float acc = 0.f;
    #pragma unroll 5
    for (int s = 0; s < fanout; ++s) {
        int row = ids ? ids[base + s] : (int)(base + s);
        acc += src[(size_t)row * ND + t];
    }
    dst[(size_t)g * ND + t] = acc * inv;
}

// ---------------------------------------------------------------------------
// C[m, colOff:colOff+128] = act( A[m,:256] @ W[256,128] + bias )
// A is either dense (ids==nullptr) or gathered rows of `Asrc` via ids[m0+m].
// Tile: 64 rows x 128 cols, BK=32, 256 threads, 4x8 micro-tile per thread.
// ldc fixed at 256 (the concat output).
// ---------------------------------------------------------------------------
__global__ void __launch_bounds__(256, 2) gemm_dual(
    const float* __restrict__ Asrc, const int* __restrict__ ids,
    const float* __restrict__ W, const float* __restrict__ bias,
    float* __restrict__ C, int colOff, int doRelu)
{
    __shared__ float As[32][65];    // [k][m], padded to kill write conflicts
    __shared__ float Bs[32][128];   // [k][n]

    const int m0  = blockIdx.x * 64;
    const int t   = threadIdx.x;
    const int tx  = t & 15;         // 16 cols of threads
    const int ty  = t >> 4;         // 16 rows of threads
    const int row0 = ty * 4;
    const int col0 = tx * 8;

    float acc[4][8];
    #pragma unroll
    for (int i = 0; i < 4; ++i)
        #pragma unroll
        for (int j = 0; j < 8; ++j) acc[i][j] = 0.f;

    // Hoist the (possibly gathered) source row index for each A-load slot.
    int arow[8];
    #pragma unroll
    for (int it = 0; it < 8; ++it) {
        int m = (t + it * 256) >> 5;
        arow[it] = ids ? ids[m0 + m] : (m0 + m);
    }

    for (int k0 = 0; k0 < ND; k0 += 32) {
        // A tile: 64 rows x 32 k  (coalesced over k, transposed into smem)
        #pragma unroll
        for (int it = 0; it < 8; ++it) {
            int idx = t + it * 256;
            int m = idx >> 5, k = idx & 31;
            As[k][m] = Asrc[(size_t)arow[it] * ND + k0 + k];
        }
        // B tile: 32 k x 128 n (coalesced over n)
        #pragma unroll
        for (int it = 0; it < 16; ++it) {
            int idx = t + it * 256;
            int k = idx >> 7, n = idx & 127;
            Bs[k][n] = W[(size_t)(k0 + k) * NH + n];
        }
        __syncthreads();

        #pragma unroll
        for (int k = 0; k < 32; ++k) {
            float av[4];
            av[0] = As[k][row0 + 0];
            av[1] = As[k][row0 + 1];
            av[2] = As[k][row0 + 2];
            av[3] = As[k][row0 + 3];
            float4 b0 = *(const float4*)&Bs[k][col0];
            float4 b1 = *(const float4*)&Bs[k][col0 + 4];
            float bv[8] = {b0.x, b0.y, b0.z, b0.w, b1.x, b1.y, b1.z, b1.w};
            #pragma unroll
            for (int i = 0; i < 4; ++i)
                #pragma unroll
                for (int j = 0; j < 8; ++j)
                    acc[i][j] = fmaf(av[i], bv[j], acc[i][j]);
        }
        __syncthreads();
    }

    // Epilogue: bias (+relu), vectorized store into the concat output
    float bb[8];
    #pragma unroll
    for (int j = 0; j < 8; ++j) bb[j] = bias[col0 + j];

    #pragma unroll
    for (int i = 0; i < 4; ++i) {
        float v[8];
        #pragma unroll
        for (int j = 0; j < 8; ++j) {
            float x = acc[i][j] + bb[j];
            v[j] = doRelu ? fmaxf(x, 0.f) : x;
        }
        float* dst = &C[(size_t)(m0 + row0 + i) * ND + colOff + col0];
        *(float4*)(dst)     = make_float4(v[0], v[1], v[2], v[3]);
        *(float4*)(dst + 4) = make_float4(v[4], v[5], v[6], v[7]);
    }
}

// ---------------------------------------------------------------------------
// out[b, c] = f0[b,:256] @ Wfc[256,64] + bfc    (4 batch rows per block)
// ---------------------------------------------------------------------------
__global__ void __launch_bounds__(256) out_head(
    const float* __restrict__ f0, const float* __restrict__ Wfc,
    const float* __restrict__ bfc, float* __restrict__ out)
{
    __shared__ float rows[4][ND];
    const int b0 = blockIdx.x * 4;
    const int t  = threadIdx.x;
    #pragma unroll
    for (int i = 0; i < 4; ++i)
        rows[i][t] = f0[(size_t)(b0 + i) * ND + t];
    __syncthreads();

    const int r = t >> 6;      // 0..3
    const int c = t & 63;      // 0..63
    float acc = bfc[c];
    #pragma unroll 8
    for (int k = 0; k < ND; ++k)
        acc = fmaf(rows[r][k], Wfc[(size_t)k * NC + c], acc);
    out[(size_t)(b0 + r) * NC + c] = acc;
}

// ---------------------------------------------------------------------------
extern "C" void kernel_launch(void* const* d_in, const int* in_sizes, int n_in,
                              void* d_out, int out_size)
{
    const int*   ids0 = (const int*)  d_in[0];
    const int*   ids1 = (const int*)  d_in[1];
    const int*   ids2 = (const int*)  d_in[2];
    const float* feat = (const float*)d_in[3];
    const float* Wx1  = (const float*)d_in[4];
    const float* bx1  = (const float*)d_in[5];
    const float* Wn1  = (const float*)d_in[6];
    const float* bn1  = (const float*)d_in[7];
    const float* Wx2  = (const float*)d_in[8];
    const float* bx2  = (const float*)d_in[9];
    const float* Wn2  = (const float*)d_in[10];
    const float* bn2  = (const float*)d_in[11];
    const float* Wfc  = (const float*)d_in[12];
    const float* bfc  = (const float*)d_in[13];
    float* out = (float*)d_out;

    float *m1, *m0, *g1, *g0, *gm, *f0;
    cudaGetSymbolAddress((void**)&m1, g_m1);
    cudaGetSymbolAddress((void**)&m0, g_m0);
    cudaGetSymbolAddress((void**)&g1, g_g1);
    cudaGetSymbolAddress((void**)&g0, g_g0);
    cudaGetSymbolAddress((void**)&gm, g_gm);
    cudaGetSymbolAddress((void**)&f0, g_f0);

    // hop-2 mean:  m1[25600,256] = mean_{s<10} feat[ids2]
    mean_gather<<<M1, ND>>>(feat, ids2, m1, NS2, 1.0f / NS2);
    // hop-1 mean:  m0[1024,256]  = mean_{s<25} feat[ids1]
    mean_gather<<<NB, ND>>>(feat, ids1, m0, NS1, 1.0f / NS1);

    // layer 1 on hop-1 set: g1 = relu([feat[ids1]@Wx1+bx1 , m1@Wn1+bn1])
    gemm_dual<<<M1 / 64, 256>>>(feat, ids1, Wx1, bx1, g1, 0,  1);
    gemm_dual<<<M1 / 64, 256>>>(m1, nullptr, Wn1, bn1, g1, NH, 1);

    // layer 1 on batch set: g0 = relu([feat[ids0]@Wx1+bx1 , m0@Wn1+bn1])
    gemm_dual<<<NB / 64, 256>>>(feat, ids0, Wx1, bx1, g0, 0,  1);
    gemm_dual<<<NB / 64, 256>>>(m0, nullptr, Wn1, bn1, g0, NH, 1);

    // mean over S1 of g1
    mean_gather<<<NB, ND>>>(g1, nullptr, gm, NS1, 1.0f / NS1);

    // layer 2 (no activation): f0 = [g0@Wx2+bx2 , gm@Wn2+bn2]
    gemm_dual<<<NB / 64, 256>>>(g0, nullptr, Wx2, bx2, f0, 0,  0);
    gemm_dual<<<NB / 64, 256>>>(gm, nullptr, Wn2, bn2, f0, NH, 0);

    // head
    out_head<<<NB / 4, 256>>>(f0, Wfc, bfc, out);
}